// round 8
// baseline (speedup 1.0000x reference)
#include <cuda_runtime.h>
#include <cuda_bf16.h>
#include <cstdint>

// QuantumFeatureMap closed form: t_q = cos(1.57*x_q), row outputs:
//   [t1t2t3, t0t1, t0t1t2, t0t1t2t3, t0t2t3, t0t3, t0, t2, t2t3, t3]
//
// R7 -> R8: keep smem staging (perfect STG coalescing) but replace the per-warp
// LDS->STG epilogue with ONE cp.async.bulk (TMA) store of the contiguous
// 10240-byte tile block. Halves L1/LSU wavefront traffic and removes the
// LDS->STG serial tail. Double-buffered staging + bulk_wait_group.read for
// reuse; depth-2 cp.async input ring.

#define QFM_ALPHA 1.57f
#define QFM_BLOCK 256
#define QFM_ITERS 4
#define QFM_TILE_BYTES (QFM_BLOCK * 10 * 4)   // 10240

template <int N>
__device__ __forceinline__ void cp_wait_group() {
    asm volatile("cp.async.wait_group %0;\n" :: "n"(N) : "memory");
}

__global__ void __launch_bounds__(QFM_BLOCK)
qfm_kernel(const float4* __restrict__ x, float* __restrict__ out, int n_tiles)
{
    __shared__ __align__(16)  float4 ins[2][QFM_BLOCK];          // 8 KB input ring
    __shared__ __align__(128) float  stage[2][QFM_BLOCK * 10];   // 20 KB staging

    const int tid   = threadIdx.x;
    const int tile0 = blockIdx.x * QFM_ITERS;

    // Prologue: tiles 0,1 into ring buffers 0,1 (one commit group each).
    #pragma unroll
    for (int p = 0; p < 2; ++p) {
        uint32_t dst = (uint32_t)__cvta_generic_to_shared(&ins[p][tid]);
        const float4* src = x + (size_t)(tile0 + p) * QFM_BLOCK + tid;
        asm volatile("cp.async.cg.shared.global [%0], [%1], 16;\n"
                     :: "r"(dst), "l"(src) : "memory");
        asm volatile("cp.async.commit_group;\n" ::: "memory");
    }

    #pragma unroll
    for (int it = 0; it < QFM_ITERS; ++it) {
        const int buf = it & 1;

        // Input for tile (tile0+it) has landed when <=1 group outstanding.
        cp_wait_group<1>();
        float4 v = ins[buf][tid];   // own bytes only -> no barrier needed

        // Prefetch tile it+2 into the buffer just consumed (same-thread,
        // same-address: LDS above is ordered before this cp.async).
        {
            const int ntile = tile0 + it + 2;
            if (ntile < n_tiles) {
                uint32_t dst = (uint32_t)__cvta_generic_to_shared(&ins[buf][tid]);
                const float4* src = x + (size_t)ntile * QFM_BLOCK + tid;
                asm volatile("cp.async.cg.shared.global [%0], [%1], 16;\n"
                             :: "r"(dst), "l"(src) : "memory");
            }
            asm volatile("cp.async.commit_group;\n" ::: "memory"); // keep group count uniform
        }

        float t0 = __cosf(QFM_ALPHA * v.x);
        float t1 = __cosf(QFM_ALPHA * v.y);
        float t2 = __cosf(QFM_ALPHA * v.z);
        float t3 = __cosf(QFM_ALPHA * v.w);

        float t01 = t0 * t1;
        float t23 = t2 * t3;

        // Before overwriting stage[buf]: the bulk store issued 2 iters ago from
        // this buffer must have finished READING smem. Allow 1 group in flight.
        if (tid == 0)
            asm volatile("cp.async.bulk.wait_group.read 1;\n" ::: "memory");
        __syncthreads();   // barrier A: reuse-safe + all threads aligned

        float2* p = (float2*)(&stage[buf][tid * 10]);   // 40B row, 8B aligned,
        p[0] = make_float2(t1 * t23, t01);              // conflict-free STS.64
        p[1] = make_float2(t01 * t2, t01 * t23);
        p[2] = make_float2(t0 * t23, t0 * t3);
        p[3] = make_float2(t0, t2);
        p[4] = make_float2(t23, t3);

        __syncthreads();   // barrier B: staging complete

        if (tid == 0) {
            // Order generic STS above against the async proxy, then bulk-store
            // the whole contiguous 10240B tile in one TMA op.
            asm volatile("fence.proxy.async.shared::cta;\n" ::: "memory");
            uint32_t src = (uint32_t)__cvta_generic_to_shared(&stage[buf][0]);
            float* gdst = out + (size_t)(tile0 + it) * (QFM_BLOCK * 10);
            asm volatile("cp.async.bulk.global.shared::cta.bulk_group [%0], [%1], %2;\n"
                         :: "l"(gdst), "r"(src), "n"(QFM_TILE_BYTES) : "memory");
            asm volatile("cp.async.bulk.commit_group;\n" ::: "memory");
        }
        // No trailing barrier: next iter's barrier A covers buffer reuse.
    }
    // Outstanding bulk stores drain automatically at kernel completion.
}

extern "C" void kernel_launch(void* const* d_in, const int* in_sizes, int n_in,
                              void* d_out, int out_size)
{
    const float4* x = (const float4*)d_in[0];
    float* out = (float*)d_out;

    const int n_rows  = in_sizes[0] / 4;                 // 1048576
    const int n_tiles = n_rows / QFM_BLOCK;              // 4096
    const int grid    = n_tiles / QFM_ITERS;             // 1024

    qfm_kernel<<<grid, QFM_BLOCK>>>(x, out, n_tiles);
}

// round 9
// speedup vs baseline: 1.1802x; 1.1802x over previous
#include <cuda_runtime.h>
#include <cuda_bf16.h>
#include <cstdint>

// QuantumFeatureMap closed form: t_q = cos(1.57*x_q), row outputs:
//   [t1t2t3, t0t1, t0t1t2, t0t1t2t3, t0t2t3, t0t3, t0, t2, t2t3, t3]
//
// R8 -> R9: R7 skeleton (best: 1024 CTAs x 4 tiles, cp.async.cg front-batched
// input ring, warp-local smem staging, coalesced 128-bit stores) with
// streaming store policy: st.global.cs (evict-first) on the output so the
// 40MB write stream drains to DRAM eagerly instead of sitting dirty in L2,
// overlapping writeback with the next graph replay's reads.

#define QFM_ALPHA 1.57f
#define QFM_BLOCK 256
#define QFM_ITERS 4

template <int N>
__device__ __forceinline__ void cp_wait_group() {
    asm volatile("cp.async.wait_group %0;\n" :: "n"(N) : "memory");
}

__device__ __forceinline__ void stg_cs_v4(float4* p, float4 v) {
    asm volatile("st.global.cs.v4.f32 [%0], {%1, %2, %3, %4};\n"
                 :: "l"(p), "f"(v.x), "f"(v.y), "f"(v.z), "f"(v.w) : "memory");
}

__global__ void __launch_bounds__(QFM_BLOCK)
qfm_kernel(const float4* __restrict__ x, float4* __restrict__ out)
{
    __shared__ __align__(16) float4 ins[QFM_ITERS][QFM_BLOCK];  // 16 KB input ring
    __shared__ __align__(16) float  st[QFM_BLOCK * 10];         // 10 KB store staging

    const int tid  = threadIdx.x;
    const int warp = tid >> 5;
    const int lane = tid & 31;
    const int tile0 = blockIdx.x * QFM_ITERS;

    // Front-batch all tile loads: 4 x 16B cp.async per thread, one group each.
    #pragma unroll
    for (int it = 0; it < QFM_ITERS; ++it) {
        uint32_t dst = (uint32_t)__cvta_generic_to_shared(&ins[it][tid]);
        const float4* src = x + (size_t)(tile0 + it) * QFM_BLOCK + tid;
        asm volatile("cp.async.cg.shared.global [%0], [%1], 16;\n"
                     :: "r"(dst), "l"(src) : "memory");
        asm volatile("cp.async.commit_group;\n" ::: "memory");
    }

    float*  ws  = st + warp * 320;            // warp's 32 rows * 10 floats
    float4* wsv = (float4*)ws;                // 80 float4
    float2* wsp = (float2*)(ws + lane * 10);  // this lane's row (40B)

    #pragma unroll
    for (int it = 0; it < QFM_ITERS; ++it) {
        // Wait until this tile's group has landed (later groups stay in flight).
        if      (it == 0) cp_wait_group<QFM_ITERS - 1>();
        else if (it == 1) cp_wait_group<QFM_ITERS - 2>();
        else if (it == 2) cp_wait_group<QFM_ITERS - 3>();
        else              cp_wait_group<0>();

        float4 v = ins[it][tid];              // own bytes -> no barrier needed

        float t0 = __cosf(QFM_ALPHA * v.x);
        float t1 = __cosf(QFM_ALPHA * v.y);
        float t2 = __cosf(QFM_ALPHA * v.z);
        float t3 = __cosf(QFM_ALPHA * v.w);

        float t01 = t0 * t1;
        float t23 = t2 * t3;

        __syncwarp();   // previous iteration's LDS (epilogue) done before overwrite

        wsp[0] = make_float2(t1 * t23, t01);        // out0, out1
        wsp[1] = make_float2(t01 * t2, t01 * t23);  // out2, out3
        wsp[2] = make_float2(t0 * t23, t0 * t3);    // out4, out5
        wsp[3] = make_float2(t0, t2);               // out6, out7
        wsp[4] = make_float2(t23, t3);              // out8, out9

        __syncwarp();   // staging visible warp-wide

        // Warp's output span: 32 rows * 40B = 1280B contiguous = 80 float4.
        // Fully coalesced, streaming (evict-first) 128-bit stores.
        float4* o = out + (size_t)(tile0 + it) * 640 + warp * 80;
        stg_cs_v4(o + lane,      wsv[lane]);
        stg_cs_v4(o + lane + 32, wsv[lane + 32]);
        if (lane < 16)
            stg_cs_v4(o + lane + 64, wsv[lane + 64]);
    }
}

extern "C" void kernel_launch(void* const* d_in, const int* in_sizes, int n_in,
                              void* d_out, int out_size)
{
    const float4* x = (const float4*)d_in[0];
    float4* out = (float4*)d_out;

    const int n_rows = in_sizes[0] / 4;                   // 1048576
    const int grid = n_rows / (QFM_BLOCK * QFM_ITERS);    // 1024 CTAs

    qfm_kernel<<<grid, QFM_BLOCK>>>(x, out);
}